// round 2
// baseline (speedup 1.0000x reference)
#include <cuda_runtime.h>
#include <math.h>

// ---------------------------------------------------------------------------
// Problem constants
// ---------------------------------------------------------------------------
#define B_   2
#define T_   2048
#define D_   1024
#define H_   16
#define NKV  64
#define NF_  4096
#define MBT  (B_ * T_)        // 4096 rows (b,t) flattened

// ---------------------------------------------------------------------------
// Scratch buffers (device globals; allocation is forbidden).
// Kernels reference these directly via gbuf(id) -- no cudaGetSymbolAddress.
// ---------------------------------------------------------------------------
__device__ float g_q[(size_t)B_ * H_ * T_ * NKV];     // [B,H,T,64]
__device__ float g_k[(size_t)B_ * H_ * T_ * NKV];
__device__ float g_v[(size_t)B_ * H_ * T_ * NKV];
__device__ float g_ocat[(size_t)MBT * D_];            // [B,T,H*64] concat heads
__device__ float g_attn[(size_t)MBT * D_];            // o-proj output
__device__ float g_h[(size_t)MBT * D_];               // after LN1
__device__ float g_f[(size_t)MBT * NF_];              // relu(h@W1+b1)
__device__ float g_y[(size_t)MBT * D_];               // ffn output

#define ID_Q    0
#define ID_K    1
#define ID_V    2
#define ID_OCAT 3
#define ID_ATTN 4
#define ID_H    5
#define ID_F    6
#define ID_Y    7

__device__ __forceinline__ float* gbuf(int id) {
    switch (id) {
        case ID_Q:    return g_q;
        case ID_K:    return g_k;
        case ID_V:    return g_v;
        case ID_OCAT: return g_ocat;
        case ID_ATTN: return g_attn;
        case ID_H:    return g_h;
        case ID_F:    return g_f;
        default:      return g_y;
    }
}

// ---------------------------------------------------------------------------
// QKV projection GEMM: per (batch, head): C[2048,64] = X[2048,1024] @ W_h[1024,64] + b_h
// BM=128, BN=64, BK=8, 256 threads, each thread computes 8x4.
// ---------------------------------------------------------------------------
__global__ __launch_bounds__(256, 2)
void qkv_gemm(const float* __restrict__ x, const float* __restrict__ W,
              const float* __restrict__ bias, int outId) {
    __shared__ __align__(16) float As[8][128];
    __shared__ __align__(16) float Bs[8][64];

    float* out = gbuf(outId);
    const int b  = blockIdx.z;
    const int h  = blockIdx.y;
    const int mt = blockIdx.x;
    const int tid = threadIdx.x;
    const int tr = tid >> 4;          // 0..15 -> rows tr*8..tr*8+7
    const int tc = tid & 15;          // 0..15 -> cols tc*4..tc*4+3

    const float* A  = x + (size_t)b * T_ * D_;
    const float* Bm = W + (size_t)h * D_ * NKV;
    float*       C  = out + ((size_t)(b * H_ + h) * T_ + (size_t)mt * 128) * NKV;
    const float* bh = bias + h * NKV;

    const int ar = tid >> 1;                 // 0..127 row within tile
    const int ak = (tid & 1) << 2;           // 0 or 4
    const float* Aptr = A + (size_t)(mt * 128 + ar) * D_ + ak;

    const int doB = (tid < 128);
    const int br = tid >> 4;                 // 0..7 (valid when tid<128)
    const int bc = (tid & 15) << 2;          // 0..60
    const float* Bptr = Bm + (size_t)br * NKV + bc;

    float acc[8][4];
#pragma unroll
    for (int i = 0; i < 8; i++)
#pragma unroll
        for (int j = 0; j < 4; j++) acc[i][j] = 0.f;

    for (int kk = 0; kk < D_; kk += 8) {
        float4 a = *(const float4*)(Aptr + kk);
        As[ak + 0][ar] = a.x; As[ak + 1][ar] = a.y;
        As[ak + 2][ar] = a.z; As[ak + 3][ar] = a.w;
        if (doB) {
            float4 bv4 = *(const float4*)(Bptr + (size_t)kk * NKV);
            *(float4*)&Bs[br][bc] = bv4;
        }
        __syncthreads();
#pragma unroll
        for (int k = 0; k < 8; k++) {
            float ra[8], rb[4];
            *(float4*)(ra)     = *(const float4*)&As[k][tr * 8];
            *(float4*)(ra + 4) = *(const float4*)&As[k][tr * 8 + 4];
            *(float4*)(rb)     = *(const float4*)&Bs[k][tc * 4];
#pragma unroll
            for (int i = 0; i < 8; i++)
#pragma unroll
                for (int j = 0; j < 4; j++) acc[i][j] += ra[i] * rb[j];
        }
        __syncthreads();
    }

    float cb[4];
#pragma unroll
    for (int j = 0; j < 4; j++) cb[j] = bh[tc * 4 + j];
#pragma unroll
    for (int i = 0; i < 8; i++) {
        const int row = tr * 8 + i;
#pragma unroll
        for (int j = 0; j < 4; j++)
            C[(size_t)row * NKV + tc * 4 + j] = acc[i][j] + cb[j];
    }
}

// ---------------------------------------------------------------------------
// Generic fp32 SGEMM on scratch buffers: C[M,N] = A[M,K] @ W[K,N] (+bias) (+relu)
// A and C are scratch-buffer ids; W/bias are external pointers.
// 128x128x8 tiles, 256 threads, 8x8 per thread.
// ---------------------------------------------------------------------------
template <bool RELU>
__global__ __launch_bounds__(256, 2)
void sgemm128(int aId, const float* __restrict__ Bm,
              const float* __restrict__ bias, int cId,
              int N, int K) {
    __shared__ __align__(16) float As[8][128];
    __shared__ __align__(16) float Bs[8][128];

    const float* A = gbuf(aId);
    float*       C = gbuf(cId);

    const int tid = threadIdx.x;
    const int tr = tid >> 4;
    const int tc = tid & 15;
    const int brow = blockIdx.y * 128;
    const int bcol = blockIdx.x * 128;

    const int ar = tid >> 1;
    const int ak = (tid & 1) << 2;
    const float* Aptr = A + (size_t)(brow + ar) * K + ak;

    const int brr = tid >> 5;                // 0..7
    const int bcc = (tid & 31) << 2;         // 0..124
    const float* Bptr = Bm + (size_t)brr * N + bcol + bcc;

    float acc[8][8];
#pragma unroll
    for (int i = 0; i < 8; i++)
#pragma unroll
        for (int j = 0; j < 8; j++) acc[i][j] = 0.f;

    for (int kk = 0; kk < K; kk += 8) {
        float4 a = *(const float4*)(Aptr + kk);
        As[ak + 0][ar] = a.x; As[ak + 1][ar] = a.y;
        As[ak + 2][ar] = a.z; As[ak + 3][ar] = a.w;
        float4 bv4 = *(const float4*)(Bptr + (size_t)kk * N);
        *(float4*)&Bs[brr][bcc] = bv4;
        __syncthreads();
#pragma unroll
        for (int k = 0; k < 8; k++) {
            float ra[8], rb[8];
            *(float4*)(ra)     = *(const float4*)&As[k][tr * 8];
            *(float4*)(ra + 4) = *(const float4*)&As[k][tr * 8 + 4];
            *(float4*)(rb)     = *(const float4*)&Bs[k][tc * 8];
            *(float4*)(rb + 4) = *(const float4*)&Bs[k][tc * 8 + 4];
#pragma unroll
            for (int i = 0; i < 8; i++)
#pragma unroll
                for (int j = 0; j < 8; j++) acc[i][j] += ra[i] * rb[j];
        }
        __syncthreads();
    }

    float cb[8];
#pragma unroll
    for (int j = 0; j < 8; j++)
        cb[j] = bias ? bias[bcol + tc * 8 + j] : 0.f;
#pragma unroll
    for (int i = 0; i < 8; i++) {
        const int row = brow + tr * 8 + i;
#pragma unroll
        for (int j = 0; j < 8; j++) {
            float v = acc[i][j] + cb[j];
            if (RELU) v = fmaxf(v, 0.f);
            C[(size_t)row * N + bcol + tc * 8 + j] = v;
        }
    }
}

// ---------------------------------------------------------------------------
// Causal flash attention (fp32, online softmax).
// Block = (q-tile of 64 rows) x (head) x (batch); 256 threads; d=64.
// Reads g_q/g_k/g_v, writes g_ocat in concat-head layout [B,T,H*64].
// ---------------------------------------------------------------------------
#define APAD 65
__global__ __launch_bounds__(256)
void attn_kernel() {
    extern __shared__ float sm[];
    float* Qs   = sm;
    float* Ks   = Qs + 64 * APAD;
    float* Vs   = Ks + 64 * APAD;
    float* Ss   = Vs + 64 * APAD;
    float* mrow = Ss + 64 * APAD;   // 64
    float* lrow = mrow + 64;        // 64
    float* arow = lrow + 64;        // 64

    const int qi = blockIdx.x;
    const int h  = blockIdx.y;
    const int b  = blockIdx.z;
    const int tid = threadIdx.x;
    const int tr4 = (tid >> 4) * 4;
    const int tc4 = (tid & 15) * 4;
    const float scale = 0.125f;     // 1/sqrt(64)
    const float NEG = -1e30f;

    const size_t base = (size_t)(b * H_ + h) * T_ * NKV;

    // load Q tile (64 x 64)
    for (int i = tid; i < 64 * 16; i += 256) {
        const int r = i >> 4, c4 = (i & 15) << 2;
        float4 qv = *(const float4*)(g_q + base + (size_t)(qi * 64 + r) * NKV + c4);
        Qs[r * APAD + c4 + 0] = qv.x; Qs[r * APAD + c4 + 1] = qv.y;
        Qs[r * APAD + c4 + 2] = qv.z; Qs[r * APAD + c4 + 3] = qv.w;
    }
    if (tid < 64) { mrow[tid] = NEG; lrow[tid] = 0.f; }

    float acc[4][4];
#pragma unroll
    for (int i = 0; i < 4; i++)
#pragma unroll
        for (int j = 0; j < 4; j++) acc[i][j] = 0.f;

    for (int jt = 0; jt <= qi; jt++) {
        __syncthreads();   // protect Ss/Ks/Vs reuse + Q visibility on first iter
        for (int i = tid; i < 64 * 16; i += 256) {
            const int r = i >> 4, c4 = (i & 15) << 2;
            const size_t off = base + (size_t)(jt * 64 + r) * NKV + c4;
            float4 kv = *(const float4*)(g_k + off);
            float4 vv = *(const float4*)(g_v + off);
            Ks[r * APAD + c4 + 0] = kv.x; Ks[r * APAD + c4 + 1] = kv.y;
            Ks[r * APAD + c4 + 2] = kv.z; Ks[r * APAD + c4 + 3] = kv.w;
            Vs[r * APAD + c4 + 0] = vv.x; Vs[r * APAD + c4 + 1] = vv.y;
            Vs[r * APAD + c4 + 2] = vv.z; Vs[r * APAD + c4 + 3] = vv.w;
        }
        __syncthreads();

        // S = Q K^T * scale  (each thread 4x4)
        float s[4][4];
#pragma unroll
        for (int i = 0; i < 4; i++)
#pragma unroll
            for (int j = 0; j < 4; j++) s[i][j] = 0.f;
#pragma unroll 8
        for (int d = 0; d < 64; d++) {
            float rq[4], rk[4];
#pragma unroll
            for (int i = 0; i < 4; i++) rq[i] = Qs[(tr4 + i) * APAD + d];
#pragma unroll
            for (int j = 0; j < 4; j++) rk[j] = Ks[(tc4 + j) * APAD + d];
#pragma unroll
            for (int i = 0; i < 4; i++)
#pragma unroll
                for (int j = 0; j < 4; j++) s[i][j] += rq[i] * rk[j];
        }
        const bool diag = (jt == qi);
#pragma unroll
        for (int i = 0; i < 4; i++) {
            const int rr = tr4 + i;
#pragma unroll
            for (int j = 0; j < 4; j++) {
                const int cc = tc4 + j;
                float val = s[i][j] * scale;
                if (diag && cc > rr) val = NEG;
                Ss[rr * APAD + cc] = val;
            }
        }
        __syncthreads();

        // online softmax (one thread per row)
        if (tid < 64) {
            const int r = tid;
            float mo = mrow[r], mx = mo;
            for (int c = 0; c < 64; c++) mx = fmaxf(mx, Ss[r * APAD + c]);
            const float al = __expf(mo - mx);
            float sum = 0.f;
            for (int c = 0; c < 64; c++) {
                float p = __expf(Ss[r * APAD + c] - mx);
                Ss[r * APAD + c] = p;
                sum += p;
            }
            lrow[r] = lrow[r] * al + sum;
            mrow[r] = mx;
            arow[r] = al;
        }
        __syncthreads();

        // rescale accumulators, then O += P @ V
#pragma unroll
        for (int i = 0; i < 4; i++) {
            const float al = arow[tr4 + i];
#pragma unroll
            for (int j = 0; j < 4; j++) acc[i][j] *= al;
        }
#pragma unroll 8
        for (int c = 0; c < 64; c++) {
            float rp[4], rv[4];
#pragma unroll
            for (int i = 0; i < 4; i++) rp[i] = Ss[(tr4 + i) * APAD + c];
#pragma unroll
            for (int j = 0; j < 4; j++) rv[j] = Vs[c * APAD + tc4 + j];
#pragma unroll
            for (int i = 0; i < 4; i++)
#pragma unroll
                for (int j = 0; j < 4; j++) acc[i][j] += rp[i] * rv[j];
        }
    }

    // normalize and write into concat layout [B, T, H*64]
#pragma unroll
    for (int i = 0; i < 4; i++) {
        const int rr = tr4 + i;
        const float inv = 1.f / lrow[rr];
        const size_t rowoff = ((size_t)b * T_ + (size_t)qi * 64 + rr) * D_ + h * NKV;
#pragma unroll
        for (int j = 0; j < 4; j++)
            g_ocat[rowoff + tc4 + j] = acc[i][j] * inv;
    }
}

// ---------------------------------------------------------------------------
// LayerNorm:  pre = a + (res?) + (cbias?);  z = LN(pre)*g + beta;
//             out = z + (addPre ? pre : 0)
// a is a scratch id; out is either a scratch id (outId>=0) or external ptr.
// One block per row, 256 threads.
// ---------------------------------------------------------------------------
__device__ __forceinline__ float block_sum(float v, float* red) {
    __syncthreads();
#pragma unroll
    for (int o = 16; o > 0; o >>= 1) v += __shfl_down_sync(0xffffffffu, v, o);
    if ((threadIdx.x & 31) == 0) red[threadIdx.x >> 5] = v;
    __syncthreads();
    if (threadIdx.x < 32) {
        float w = (threadIdx.x < 8) ? red[threadIdx.x] : 0.f;
#pragma unroll
        for (int o = 4; o > 0; o >>= 1) w += __shfl_down_sync(0xffffffffu, w, o);
        if (threadIdx.x == 0) red[0] = w;
    }
    __syncthreads();
    return red[0];
}

__global__ __launch_bounds__(256)
void ln_kernel(int aId, const float* __restrict__ res,
               const float* __restrict__ cbias, const float* __restrict__ g,
               const float* __restrict__ beta,
               float* __restrict__ out_ext, int outId, int addPre) {
    __shared__ float pre[D_];
    __shared__ float red[32];
    const int row = blockIdx.x;
    const int tid = threadIdx.x;
    const float* ap = gbuf(aId) + (size_t)row * D_;
    const float* rp = res ? res + (size_t)row * D_ : nullptr;
    float* out = (outId >= 0) ? gbuf(outId) : out_ext;

    float ls = 0.f;
    for (int i = tid; i < D_; i += 256) {
        float v = ap[i];
        if (rp)    v += rp[i];
        if (cbias) v += cbias[i];
        pre[i] = v;
        ls += v;
    }
    const float mean = block_sum(ls, red) * (1.f / D_);
    float lv = 0.f;
    for (int i = tid; i < D_; i += 256) {
        const float d = pre[i] - mean;
        lv += d * d;
    }
    const float var = block_sum(lv, red) * (1.f / D_);
    const float rstd = rsqrtf(var + 1e-5f);
    for (int i = tid; i < D_; i += 256) {
        const float p = pre[i];
        const float z = (p - mean) * rstd * g[i] + beta[i];
        out[(size_t)row * D_ + i] = z + (addPre ? p : 0.f);
    }
}

// ---------------------------------------------------------------------------
// Launcher -- kernel launches only (plus one capture-safe attribute set).
// ---------------------------------------------------------------------------
extern "C" void kernel_launch(void* const* d_in, const int* in_sizes, int n_in,
                              void* d_out, int out_size) {
    const float* x    = (const float*)d_in[0];
    const float* Wq   = (const float*)d_in[1];
    const float* bq   = (const float*)d_in[2];
    const float* Wk   = (const float*)d_in[3];
    const float* bk   = (const float*)d_in[4];
    const float* Wv   = (const float*)d_in[5];
    const float* bv   = (const float*)d_in[6];
    const float* Wo   = (const float*)d_in[7];
    const float* bo   = (const float*)d_in[8];
    const float* ln1g = (const float*)d_in[9];
    const float* ln1b = (const float*)d_in[10];
    const float* W1   = (const float*)d_in[11];
    const float* b1   = (const float*)d_in[12];
    const float* W2   = (const float*)d_in[13];
    const float* b2   = (const float*)d_in[14];
    const float* ln2g = (const float*)d_in[15];
    const float* ln2b = (const float*)d_in[16];
    float* out = (float*)d_out;

    // 1) QKV projections (per-head GEMMs)
    dim3 qkvGrid(T_ / 128, H_, B_);
    qkv_gemm<<<qkvGrid, 256>>>(x, Wq, bq, ID_Q);
    qkv_gemm<<<qkvGrid, 256>>>(x, Wk, bk, ID_K);
    qkv_gemm<<<qkvGrid, 256>>>(x, Wv, bv, ID_V);

    // 2) Flash attention (causal)
    const int smem = (4 * 64 * APAD + 3 * 64) * (int)sizeof(float);  // 67328
    cudaFuncSetAttribute(attn_kernel,
                         cudaFuncAttributeMaxDynamicSharedMemorySize, smem);
    attn_kernel<<<dim3(T_ / 64, H_, B_), 256, smem>>>();

    // 3) Output projection (bo folded into LN1)
    sgemm128<false><<<dim3(D_ / 128, MBT / 128), 256>>>(ID_OCAT, Wo, nullptr, ID_ATTN, D_, D_);

    // 4) h = LN(x + attn_out + bo)
    ln_kernel<<<MBT, 256>>>(ID_ATTN, x, bo, ln1g, ln1b, nullptr, ID_H, 0);

    // 5) FFN
    sgemm128<true ><<<dim3(NF_ / 128, MBT / 128), 256>>>(ID_H, W1, b1, ID_F, NF_, D_);
    sgemm128<false><<<dim3(D_  / 128, MBT / 128), 256>>>(ID_F, W2, b2, ID_Y, D_, NF_);

    // 6) out = LN(y) + y
    ln_kernel<<<MBT, 256>>>(ID_Y, nullptr, nullptr, ln2g, ln2b, out, -1, 1);
}

// round 3
// speedup vs baseline: 1.2326x; 1.2326x over previous
#include <cuda_runtime.h>
#include <math.h>
#include <stdint.h>

// ---------------------------------------------------------------------------
// Problem constants
// ---------------------------------------------------------------------------
#define B_   2
#define T_   2048
#define D_   1024
#define H_   16
#define NKV  64
#define NF_  4096
#define MBT  (B_ * T_)        // 4096 rows (b,t) flattened

// ---------------------------------------------------------------------------
// Scratch buffers (device globals; allocation is forbidden).
// ---------------------------------------------------------------------------
__device__ float g_q[(size_t)B_ * H_ * T_ * NKV];     // [B,H,T,64]
__device__ float g_k[(size_t)B_ * H_ * T_ * NKV];
__device__ float g_v[(size_t)B_ * H_ * T_ * NKV];
__device__ float g_ocat[(size_t)MBT * D_];            // [B,T,H*64] concat heads
__device__ float g_attn[(size_t)MBT * D_];            // o-proj output
__device__ float g_h[(size_t)MBT * D_];               // after LN1
__device__ float g_f[(size_t)MBT * NF_];              // relu(h@W1+b1)
__device__ float g_y[(size_t)MBT * D_];               // ffn output

#define ID_Q    0
#define ID_K    1
#define ID_V    2
#define ID_OCAT 3
#define ID_ATTN 4
#define ID_H    5
#define ID_F    6
#define ID_Y    7

__device__ __forceinline__ float* gbuf(int id) {
    switch (id) {
        case ID_Q:    return g_q;
        case ID_K:    return g_k;
        case ID_V:    return g_v;
        case ID_OCAT: return g_ocat;
        case ID_ATTN: return g_attn;
        case ID_H:    return g_h;
        case ID_F:    return g_f;
        default:      return g_y;
    }
}

// ---------------------------------------------------------------------------
// tf32 helpers (3xTF32 split: v = hi + lo, both tf32-representable)
// ---------------------------------------------------------------------------
__device__ __forceinline__ void split_tf32(float v, uint32_t& hi, uint32_t& lo) {
    uint32_t uh = __float_as_uint(v) & 0xffffe000u;
    hi = uh;
    lo = __float_as_uint(v - __uint_as_float(uh)) & 0xffffe000u;
}

__device__ __forceinline__ void mma_tf32(float* c, const uint32_t* a,
                                         uint32_t b0, uint32_t b1) {
    asm volatile(
        "mma.sync.aligned.m16n8k8.row.col.f32.tf32.tf32.f32 "
        "{%0,%1,%2,%3}, {%4,%5,%6,%7}, {%8,%9}, {%0,%1,%2,%3};\n"
        : "+f"(c[0]), "+f"(c[1]), "+f"(c[2]), "+f"(c[3])
        : "r"(a[0]), "r"(a[1]), "r"(a[2]), "r"(a[3]), "r"(b0), "r"(b1));
}

// ---------------------------------------------------------------------------
// Tensor-core GEMM (3xTF32): C[M,N] = A[M,K] @ B[K,N] (+bias) (+relu)
// BM=128, BN=128, BK=16, 256 threads (8 warps, 4x2), warp tile 32x64.
// bmode: 0 = B row-major [K,N];  1 = B packed per-head [H, K, 64] (QKV weights)
// cmode: 0 = C row-major [M,N];  1 = C scattered to [B,H,T,64] (QKV outputs)
// ---------------------------------------------------------------------------
__global__ __launch_bounds__(256)
void gemm_tc(const float* __restrict__ Aext, int aId,
             const float* __restrict__ Bm, const float* __restrict__ bias,
             int cId, int N, int K, int bmode, int cmode, int relu)
{
    __shared__ float As[128][20];   // [m][k], k stride 20 -> conflict-free frags
    __shared__ float Bs[128][20];   // [n][k]

    const float* Ab = (aId >= 0) ? gbuf(aId) : Aext;
    float*       Cb = gbuf(cId);

    const int tid  = threadIdx.x;
    const int brow = blockIdx.y * 128;
    const int bcol = blockIdx.x * 128;

    // global->smem assignments
    const int am = tid >> 1;                 // 0..127
    const int akq = (tid & 1) * 8;           // 0 or 8
    const float* Aptr = Ab + (size_t)(brow + am) * K + akq;

    const int kb = tid & 15;                 // B k-row 0..15
    const int ng = tid >> 4;                 // 0..15
    const int n0 = ng * 8;                   // 8 cols per thread

    // warp/frag coords
    const int warp = tid >> 5;
    const int lane = tid & 31;
    const int wm = warp >> 1;                // 0..3 -> row base wm*32
    const int wn = warp & 1;                 // 0..1 -> col base wn*64
    const int grp = lane >> 2;               // 0..7
    const int tig = lane & 3;                // 0..3

    float acc[2][8][4];
#pragma unroll
    for (int mt = 0; mt < 2; mt++)
#pragma unroll
        for (int nt = 0; nt < 8; nt++)
#pragma unroll
            for (int i = 0; i < 4; i++) acc[mt][nt][i] = 0.f;

    for (int kk = 0; kk < K; kk += 16) {
        // global loads
        float4 av0 = *(const float4*)(Aptr + kk);
        float4 av1 = *(const float4*)(Aptr + kk + 4);
        float4 bv0, bv1;
        if (bmode == 0) {
            const float* bp = Bm + (size_t)(kk + kb) * N + bcol + n0;
            bv0 = *(const float4*)(bp);
            bv1 = *(const float4*)(bp + 4);
        } else {
            const int d  = kk + kb;
            const int j0 = bcol + n0;
            const float* bp = Bm + (size_t)(j0 >> 6) * K * 64 +
                              (size_t)d * 64 + (j0 & 63);
            bv0 = *(const float4*)(bp);
            bv1 = *(const float4*)(bp + 4);
        }

        __syncthreads();
        // A stores
        As[am][akq + 0] = av0.x; As[am][akq + 1] = av0.y;
        As[am][akq + 2] = av0.z; As[am][akq + 3] = av0.w;
        As[am][akq + 4] = av1.x; As[am][akq + 5] = av1.y;
        As[am][akq + 6] = av1.z; As[am][akq + 7] = av1.w;
        // B stores (transpose to [n][k])
        Bs[n0 + 0][kb] = bv0.x; Bs[n0 + 1][kb] = bv0.y;
        Bs[n0 + 2][kb] = bv0.z; Bs[n0 + 3][kb] = bv0.w;
        Bs[n0 + 4][kb] = bv1.x; Bs[n0 + 5][kb] = bv1.y;
        Bs[n0 + 6][kb] = bv1.z; Bs[n0 + 7][kb] = bv1.w;
        __syncthreads();

#pragma unroll
        for (int k0 = 0; k0 < 16; k0 += 8) {
            // A fragments (hi/lo)
            uint32_t ah[2][4], alo[2][4];
#pragma unroll
            for (int mt = 0; mt < 2; mt++) {
                const int r0 = wm * 32 + mt * 16 + grp;
                split_tf32(As[r0    ][k0 + tig],     ah[mt][0], alo[mt][0]);
                split_tf32(As[r0 + 8][k0 + tig],     ah[mt][1], alo[mt][1]);
                split_tf32(As[r0    ][k0 + 4 + tig], ah[mt][2], alo[mt][2]);
                split_tf32(As[r0 + 8][k0 + 4 + tig], ah[mt][3], alo[mt][3]);
            }
#pragma unroll
            for (int nt = 0; nt < 8; nt++) {
                const int n = wn * 64 + nt * 8 + grp;
                uint32_t bh0, bl0, bh1, bl1;
                split_tf32(Bs[n][k0 + tig],     bh0, bl0);
                split_tf32(Bs[n][k0 + 4 + tig], bh1, bl1);
#pragma unroll
                for (int mt = 0; mt < 2; mt++) {
                    mma_tf32(acc[mt][nt], ah[mt],  bh0, bh1);
                    mma_tf32(acc[mt][nt], ah[mt],  bl0, bl1);
                    mma_tf32(acc[mt][nt], alo[mt], bh0, bh1);
                }
            }
        }
    }

    // epilogue
#pragma unroll
    for (int mt = 0; mt < 2; mt++) {
#pragma unroll
        for (int nt = 0; nt < 8; nt++) {
            const int row = brow + wm * 32 + mt * 16 + grp;
            const int col = bcol + wn * 64 + nt * 8 + 2 * tig;
            float b0 = bias ? bias[col]     : 0.f;
            float b1 = bias ? bias[col + 1] : 0.f;
            float v00 = acc[mt][nt][0] + b0, v01 = acc[mt][nt][1] + b1;
            float v10 = acc[mt][nt][2] + b0, v11 = acc[mt][nt][3] + b1;
            if (relu) {
                v00 = fmaxf(v00, 0.f); v01 = fmaxf(v01, 0.f);
                v10 = fmaxf(v10, 0.f); v11 = fmaxf(v11, 0.f);
            }
            if (cmode == 0) {
                *(float2*)(Cb + (size_t)row * N + col)       = make_float2(v00, v01);
                *(float2*)(Cb + (size_t)(row + 8) * N + col) = make_float2(v10, v11);
            } else {
                const int h  = col >> 6, cc = col & 63;
                const int b  = row >> 11;          // T_ = 2048
                const int t  = row & 2047;
                float* p0 = Cb + ((size_t)(b * H_ + h) * T_ + t) * 64 + cc;
                *(float2*)p0            = make_float2(v00, v01);
                *(float2*)(p0 + 8 * 64) = make_float2(v10, v11);  // row+8 -> t+8
            }
        }
    }
}

// ---------------------------------------------------------------------------
// Causal flash attention (fp32, online softmax; 4 threads per softmax row).
// Block = (q-tile of 64 rows) x (head) x (batch); 256 threads; d=64.
// ---------------------------------------------------------------------------
#define APAD 65
__global__ __launch_bounds__(256)
void attn_kernel() {
    extern __shared__ float sm[];
    float* Qs   = sm;
    float* Ks   = Qs + 64 * APAD;
    float* Vs   = Ks + 64 * APAD;
    float* Ss   = Vs + 64 * APAD;
    float* mrow = Ss + 64 * APAD;   // 64
    float* lrow = mrow + 64;        // 64
    float* arow = lrow + 64;        // 64

    const int qi = blockIdx.x;
    const int h  = blockIdx.y;
    const int b  = blockIdx.z;
    const int tid = threadIdx.x;
    const int tr4 = (tid >> 4) * 4;
    const int tc4 = (tid & 15) * 4;
    const float scale = 0.125f;     // 1/sqrt(64)
    const float NEG = -1e30f;

    const size_t base = (size_t)(b * H_ + h) * T_ * NKV;

    for (int i = tid; i < 64 * 16; i += 256) {
        const int r = i >> 4, c4 = (i & 15) << 2;
        float4 qv = *(const float4*)(g_q + base + (size_t)(qi * 64 + r) * NKV + c4);
        Qs[r * APAD + c4 + 0] = qv.x; Qs[r * APAD + c4 + 1] = qv.y;
        Qs[r * APAD + c4 + 2] = qv.z; Qs[r * APAD + c4 + 3] = qv.w;
    }
    if (tid < 64) { mrow[tid] = NEG; lrow[tid] = 0.f; }

    float acc[4][4];
#pragma unroll
    for (int i = 0; i < 4; i++)
#pragma unroll
        for (int j = 0; j < 4; j++) acc[i][j] = 0.f;

    for (int jt = 0; jt <= qi; jt++) {
        __syncthreads();
        for (int i = tid; i < 64 * 16; i += 256) {
            const int r = i >> 4, c4 = (i & 15) << 2;
            const size_t off = base + (size_t)(jt * 64 + r) * NKV + c4;
            float4 kv = *(const float4*)(g_k + off);
            float4 vv = *(const float4*)(g_v + off);
            Ks[r * APAD + c4 + 0] = kv.x; Ks[r * APAD + c4 + 1] = kv.y;
            Ks[r * APAD + c4 + 2] = kv.z; Ks[r * APAD + c4 + 3] = kv.w;
            Vs[r * APAD + c4 + 0] = vv.x; Vs[r * APAD + c4 + 1] = vv.y;
            Vs[r * APAD + c4 + 2] = vv.z; Vs[r * APAD + c4 + 3] = vv.w;
        }
        __syncthreads();

        // S = Q K^T * scale (each thread 4x4)
        float s[4][4];
#pragma unroll
        for (int i = 0; i < 4; i++)
#pragma unroll
            for (int j = 0; j < 4; j++) s[i][j] = 0.f;
#pragma unroll 8
        for (int d = 0; d < 64; d++) {
            float rq[4], rk[4];
#pragma unroll
            for (int i = 0; i < 4; i++) rq[i] = Qs[(tr4 + i) * APAD + d];
#pragma unroll
            for (int j = 0; j < 4; j++) rk[j] = Ks[(tc4 + j) * APAD + d];
#pragma unroll
            for (int i = 0; i < 4; i++)
#pragma unroll
                for (int j = 0; j < 4; j++) s[i][j] += rq[i] * rk[j];
        }
        const bool diag = (jt == qi);
#pragma unroll
        for (int i = 0; i < 4; i++) {
            const int rr = tr4 + i;
#pragma unroll
            for (int j = 0; j < 4; j++) {
                const int cc = tc4 + j;
                float val = s[i][j] * scale;
                if (diag && cc > rr) val = NEG;
                Ss[rr * APAD + cc] = val;
            }
        }
        __syncthreads();

        // online softmax: 4 threads per row (quad of consecutive lanes)
        {
            const int r  = tid >> 2;
            const int cq = (tid & 3) * 16;
            float mx = NEG;
#pragma unroll
            for (int c = 0; c < 16; c++) mx = fmaxf(mx, Ss[r * APAD + cq + c]);
            mx = fmaxf(mx, __shfl_xor_sync(0xffffffffu, mx, 1));
            mx = fmaxf(mx, __shfl_xor_sync(0xffffffffu, mx, 2));
            const float mo = mrow[r];
            mx = fmaxf(mx, mo);
            float sum = 0.f;
#pragma unroll
            for (int c = 0; c < 16; c++) {
                float p = __expf(Ss[r * APAD + cq + c] - mx);
                Ss[r * APAD + cq + c] = p;
                sum += p;
            }
            sum += __shfl_xor_sync(0xffffffffu, sum, 1);
            sum += __shfl_xor_sync(0xffffffffu, sum, 2);
            if ((tid & 3) == 0) {
                const float al = __expf(mo - mx);
                lrow[r] = lrow[r] * al + sum;
                mrow[r] = mx;
                arow[r] = al;
            }
        }
        __syncthreads();

        // rescale accumulators, then O += P @ V
#pragma unroll
        for (int i = 0; i < 4; i++) {
            const float al = arow[tr4 + i];
#pragma unroll
            for (int j = 0; j < 4; j++) acc[i][j] *= al;
        }
#pragma unroll 8
        for (int c = 0; c < 64; c++) {
            float rp[4], rv[4];
#pragma unroll
            for (int i = 0; i < 4; i++) rp[i] = Ss[(tr4 + i) * APAD + c];
#pragma unroll
            for (int j = 0; j < 4; j++) rv[j] = Vs[c * APAD + tc4 + j];
#pragma unroll
            for (int i = 0; i < 4; i++)
#pragma unroll
                for (int j = 0; j < 4; j++) acc[i][j] += rp[i] * rv[j];
        }
    }

#pragma unroll
    for (int i = 0; i < 4; i++) {
        const int rr = tr4 + i;
        const float inv = 1.f / lrow[rr];
        const size_t rowoff = ((size_t)b * T_ + (size_t)qi * 64 + rr) * D_ + h * NKV;
#pragma unroll
        for (int j = 0; j < 4; j++)
            g_ocat[rowoff + tc4 + j] = acc[i][j] * inv;
    }
}

// ---------------------------------------------------------------------------
// LayerNorm (unchanged from round 1)
// ---------------------------------------------------------------------------
__device__ __forceinline__ float block_sum(float v, float* red) {
    __syncthreads();
#pragma unroll
    for (int o = 16; o > 0; o >>= 1) v += __shfl_down_sync(0xffffffffu, v, o);
    if ((threadIdx.x & 31) == 0) red[threadIdx.x >> 5] = v;
    __syncthreads();
    if (threadIdx.x < 32) {
        float w = (threadIdx.x < 8) ? red[threadIdx.x] : 0.f;
#pragma unroll
        for (int o = 4; o > 0; o >>= 1) w += __shfl_down_sync(0xffffffffu, w, o);
        if (threadIdx.x == 0) red[0] = w;
    }
    __syncthreads();
    return red[0];
}

__global__ __launch_bounds__(256)
void ln_kernel(int aId, const float* __restrict__ res,
               const float* __restrict__ cbias, const float* __restrict__ g,
               const float* __restrict__ beta,
               float* __restrict__ out_ext, int outId, int addPre) {
    __shared__ float pre[D_];
    __shared__ float red[32];
    const int row = blockIdx.x;
    const int tid = threadIdx.x;
    const float* ap = gbuf(aId) + (size_t)row * D_;
    const float* rp = res ? res + (size_t)row * D_ : nullptr;
    float* out = (outId >= 0) ? gbuf(outId) : out_ext;

    float ls = 0.f;
    for (int i = tid; i < D_; i += 256) {
        float v = ap[i];
        if (rp)    v += rp[i];
        if (cbias) v += cbias[i];
        pre[i] = v;
        ls += v;
    }
    const float mean = block_sum(ls, red) * (1.f / D_);
    float lv = 0.f;
    for (int i = tid; i < D_; i += 256) {
        const float d = pre[i] - mean;
        lv += d * d;
    }
    const float var = block_sum(lv, red) * (1.f / D_);
    const float rstd = rsqrtf(var + 1e-5f);
    for (int i = tid; i < D_; i += 256) {
        const float p = pre[i];
        const float z = (p - mean) * rstd * g[i] + beta[i];
        out[(size_t)row * D_ + i] = z + (addPre ? p : 0.f);
    }
}

// ---------------------------------------------------------------------------
// Launcher
// ---------------------------------------------------------------------------
extern "C" void kernel_launch(void* const* d_in, const int* in_sizes, int n_in,
                              void* d_out, int out_size) {
    const float* x    = (const float*)d_in[0];
    const float* Wq   = (const float*)d_in[1];
    const float* bq   = (const float*)d_in[2];
    const float* Wk   = (const float*)d_in[3];
    const float* bk   = (const float*)d_in[4];
    const float* Wv   = (const float*)d_in[5];
    const float* bv   = (const float*)d_in[6];
    const float* Wo   = (const float*)d_in[7];
    const float* bo   = (const float*)d_in[8];
    const float* ln1g = (const float*)d_in[9];
    const float* ln1b = (const float*)d_in[10];
    const float* W1   = (const float*)d_in[11];
    const float* b1   = (const float*)d_in[12];
    const float* W2   = (const float*)d_in[13];
    const float* b2   = (const float*)d_in[14];
    const float* ln2g = (const float*)d_in[15];
    const float* ln2b = (const float*)d_in[16];
    float* out = (float*)d_out;

    // 1) QKV projections: one combined 4096x1024x1024 TC GEMM each
    dim3 gNarrow(D_ / 128, MBT / 128);          // (8, 32)
    gemm_tc<<<gNarrow, 256>>>(x, -1, Wq, bq, ID_Q, D_, D_, 1, 1, 0);
    gemm_tc<<<gNarrow, 256>>>(x, -1, Wk, bk, ID_K, D_, D_, 1, 1, 0);
    gemm_tc<<<gNarrow, 256>>>(x, -1, Wv, bv, ID_V, D_, D_, 1, 1, 0);

    // 2) Flash attention (causal)
    const int smem = (4 * 64 * APAD + 3 * 64) * (int)sizeof(float);  // 67328
    cudaFuncSetAttribute(attn_kernel,
                         cudaFuncAttributeMaxDynamicSharedMemorySize, smem);
    attn_kernel<<<dim3(T_ / 64, H_, B_), 256, smem>>>();

    // 3) Output projection (bo folded into LN1)
    gemm_tc<<<gNarrow, 256>>>(nullptr, ID_OCAT, Wo, nullptr, ID_ATTN, D_, D_, 0, 0, 0);

    // 4) h = LN(x + attn_out + bo)
    ln_kernel<<<MBT, 256>>>(ID_ATTN, x, bo, ln1g, ln1b, nullptr, ID_H, 0);

    // 5) FFN
    gemm_tc<<<dim3(NF_ / 128, MBT / 128), 256>>>(nullptr, ID_H, W1, b1, ID_F, NF_, D_, 0, 0, 1);
    gemm_tc<<<gNarrow, 256>>>(nullptr, ID_F, W2, b2, ID_Y, D_, NF_, 0, 0, 0);

    // 6) out = LN(y) + y
    ln_kernel<<<MBT, 256>>>(ID_Y, nullptr, nullptr, ln2g, ln2b, out, -1, 1);
}